// round 14
// baseline (speedup 1.0000x reference)
#include <cuda_runtime.h>
#include <cuda_bf16.h>
#include <math.h>
#include <stdint.h>

// Problem constants
#define NB 32            // batch
#define TT 1024          // timesteps
#define DD 512           // input dim
#define HH 512           // hidden dim
#define G4 2048          // 4*H
#define MROWS (NB * TT)  // 32768

// Recurrent kernel config
#define RBLOCKS 128      // persistent blocks, 1 per SM
#define RTHREADS 256
#define JPB 4            // h-columns per block
#define GRPBLK 16        // blocks per K-chunk group (128/8)

// Scratch (device globals; no cudaMalloc allowed)
__device__ float g_xw[(size_t)MROWS * G4];   // 268 MB: x @ Wx + b
__device__ unsigned g_cntK[8 * 8];           // 8 group counters, 32B apart

// h exchanged in MMA A-fragment layout: [buf][mt][ktile][lane] -> uint4
__device__ uint4 g_hfragHI[2][2][32][32];
__device__ uint4 g_hfragLO[2][2][32][32];

// bf16 hi/lo split buffers for Wx only (x is converted in-GEMM)
__device__ __nv_bfloat16 g_whi[(size_t)DD * G4];
__device__ __nv_bfloat16 g_wlo[(size_t)DD * G4];

// ---------------------------------------------------------------------------
// fp32 -> bf16 hi + lo split
// ---------------------------------------------------------------------------
__device__ __forceinline__ void split1(float v, __nv_bfloat16& h, __nv_bfloat16& l)
{
    h = __float2bfloat16(v);
    l = __float2bfloat16(v - __bfloat162float(h));
}

// split 8 consecutive floats into packed hi/lo uint4 (bf16x2 x4)
__device__ __forceinline__ void split8_pack(const float* v, uint4& hi, uint4& lo)
{
    unsigned h[8], l[8];
#pragma unroll
    for (int i = 0; i < 8; i++) {
        __nv_bfloat16 hb, lb;
        split1(v[i], hb, lb);
        h[i] = __bfloat16_as_ushort(hb);
        l[i] = __bfloat16_as_ushort(lb);
    }
    hi.x = (h[1] << 16) | h[0]; hi.y = (h[3] << 16) | h[2];
    hi.z = (h[5] << 16) | h[4]; hi.w = (h[7] << 16) | h[6];
    lo.x = (l[1] << 16) | l[0]; lo.y = (l[3] << 16) | l[2];
    lo.z = (l[5] << 16) | l[4]; lo.w = (l[7] << 16) | l[6];
}

__global__ void __launch_bounds__(256) split_kernel_w(const float* __restrict__ src)
{
    size_t i = (size_t)blockIdx.x * blockDim.x + threadIdx.x;
    size_t n4 = (size_t)DD * G4 / 4;
    if (i >= n4) return;
    float4 v = ((const float4*)src)[i];
    __nv_bfloat16 h0, h1, h2, h3, l0, l1, l2, l3;
    split1(v.x, h0, l0); split1(v.y, h1, l1);
    split1(v.z, h2, l2); split1(v.w, h3, l3);
    ((__nv_bfloat162*)g_whi)[2 * i]     = __nv_bfloat162(h0, h1);
    ((__nv_bfloat162*)g_whi)[2 * i + 1] = __nv_bfloat162(h2, h3);
    ((__nv_bfloat162*)g_wlo)[2 * i]     = __nv_bfloat162(l0, l1);
    ((__nv_bfloat162*)g_wlo)[2 * i + 1] = __nv_bfloat162(l2, l3);
}

// ---------------------------------------------------------------------------
// PTX wrappers
// ---------------------------------------------------------------------------
__device__ __forceinline__ void ldsm_x4(uint32_t& r0, uint32_t& r1, uint32_t& r2,
                                        uint32_t& r3, const void* p)
{
    uint32_t a = (uint32_t)__cvta_generic_to_shared(p);
    asm volatile("ldmatrix.sync.aligned.m8n8.x4.shared.b16 {%0,%1,%2,%3}, [%4];"
                 : "=r"(r0), "=r"(r1), "=r"(r2), "=r"(r3) : "r"(a));
}

__device__ __forceinline__ void ldsm_x4_t(uint32_t& r0, uint32_t& r1, uint32_t& r2,
                                          uint32_t& r3, const void* p)
{
    uint32_t a = (uint32_t)__cvta_generic_to_shared(p);
    asm volatile("ldmatrix.sync.aligned.m8n8.x4.trans.shared.b16 {%0,%1,%2,%3}, [%4];"
                 : "=r"(r0), "=r"(r1), "=r"(r2), "=r"(r3) : "r"(a));
}

__device__ __forceinline__ void mma_bf16(float* c, const uint32_t* a,
                                         uint32_t b0, uint32_t b1)
{
    asm volatile(
        "mma.sync.aligned.m16n8k16.row.col.f32.bf16.bf16.f32 "
        "{%0,%1,%2,%3},{%4,%5,%6,%7},{%8,%9},{%0,%1,%2,%3};"
        : "+f"(c[0]), "+f"(c[1]), "+f"(c[2]), "+f"(c[3])
        : "r"(a[0]), "r"(a[1]), "r"(a[2]), "r"(a[3]), "r"(b0), "r"(b1));
}

// ---------------------------------------------------------------------------
// Phase 1 GEMM (R13, measured best): bf16 split, BM=64 x BN=128 x BK=32,
// 2 blocks/SM, register double-buffered loads; x converted IN-KERNEL.
// ---------------------------------------------------------------------------
#define P1_SA 40
#define P1_SB 136

__global__ void __launch_bounds__(256, 2) gemm_xw_mma(const float* __restrict__ x,
                                                      const float* __restrict__ bias)
{
    __shared__ __nv_bfloat16 Ah[64 * P1_SA];
    __shared__ __nv_bfloat16 Al[64 * P1_SA];
    __shared__ __nv_bfloat16 Bh[32 * P1_SB];
    __shared__ __nv_bfloat16 Bl[32 * P1_SB];

    const int tid = threadIdx.x;
    const int bn = blockIdx.x;
    const int bm = blockIdx.y;
    const int warp = tid >> 5;
    const int lane = tid & 31;
    const int wm = (warp >> 2) * 32;
    const int wn = (warp & 3) * 32;

    const int arow = tid >> 2;
    const int acol = (tid & 3) * 8;
    const int brow = tid >> 4;
    const int bcol = (tid & 15) * 8;

    const size_t a_off = (size_t)(bm * 64 + arow) * DD + acol;
    const size_t b_off0 = (size_t)brow * G4 + bn * 128 + bcol;

    float acc[2][4][4];
#pragma unroll
    for (int mi = 0; mi < 2; mi++)
#pragma unroll
        for (int n = 0; n < 4; n++)
#pragma unroll
            for (int q = 0; q < 4; q++) acc[mi][n][q] = 0.0f;

    const int a_lrow = lane & 15;
    const int a_lcol = (lane >> 4) << 3;

    float4 rx0 = *(const float4*)&x[a_off];
    float4 rx1 = *(const float4*)&x[a_off + 4];
    uint4 rb_h[2], rb_l[2];
#pragma unroll
    for (int i = 0; i < 2; i++) {
        size_t go = b_off0 + (size_t)(i * 16) * G4;
        rb_h[i] = *(const uint4*)&g_whi[go];
        rb_l[i] = *(const uint4*)&g_wlo[go];
    }

    for (int k0 = 0; k0 < DD; k0 += 32) {
        {
            float xv[8] = {rx0.x, rx0.y, rx0.z, rx0.w, rx1.x, rx1.y, rx1.z, rx1.w};
            uint4 ah4, al4;
            split8_pack(xv, ah4, al4);
            *(uint4*)&Ah[arow * P1_SA + acol] = ah4;
            *(uint4*)&Al[arow * P1_SA + acol] = al4;
        }
#pragma unroll
        for (int i = 0; i < 2; i++) {
            *(uint4*)&Bh[(brow + i * 16) * P1_SB + bcol] = rb_h[i];
            *(uint4*)&Bl[(brow + i * 16) * P1_SB + bcol] = rb_l[i];
        }
        __syncthreads();

        if (k0 + 32 < DD) {
            rx0 = *(const float4*)&x[a_off + k0 + 32];
            rx1 = *(const float4*)&x[a_off + k0 + 36];
#pragma unroll
            for (int i = 0; i < 2; i++) {
                size_t go = b_off0 + (size_t)(k0 + 32 + i * 16) * G4;
                rb_h[i] = *(const uint4*)&g_whi[go];
                rb_l[i] = *(const uint4*)&g_wlo[go];
            }
        }

#pragma unroll
        for (int kk = 0; kk < 32; kk += 16) {
            uint32_t ah[2][4], al[2][4], bh[2][4], bl[2][4];
#pragma unroll
            for (int mi = 0; mi < 2; mi++) {
                const __nv_bfloat16* pa =
                    &Ah[(wm + mi * 16 + a_lrow) * P1_SA + kk + a_lcol];
                ldsm_x4(ah[mi][0], ah[mi][1], ah[mi][2], ah[mi][3], pa);
                const __nv_bfloat16* pl =
                    &Al[(wm + mi * 16 + a_lrow) * P1_SA + kk + a_lcol];
                ldsm_x4(al[mi][0], al[mi][1], al[mi][2], al[mi][3], pl);
            }
#pragma unroll
            for (int g = 0; g < 2; g++) {
                const __nv_bfloat16* pb =
                    &Bh[(kk + a_lrow) * P1_SB + wn + g * 16 + a_lcol];
                ldsm_x4_t(bh[g][0], bh[g][1], bh[g][2], bh[g][3], pb);
                const __nv_bfloat16* pbl =
                    &Bl[(kk + a_lrow) * P1_SB + wn + g * 16 + a_lcol];
                ldsm_x4_t(bl[g][0], bl[g][1], bl[g][2], bl[g][3], pbl);
            }
#pragma unroll
            for (int mi = 0; mi < 2; mi++)
#pragma unroll
                for (int n = 0; n < 4; n++) {
                    uint32_t b0 = bh[n >> 1][(n & 1) * 2];
                    uint32_t b1 = bh[n >> 1][(n & 1) * 2 + 1];
                    uint32_t c0 = bl[n >> 1][(n & 1) * 2];
                    uint32_t c1 = bl[n >> 1][(n & 1) * 2 + 1];
                    mma_bf16(acc[mi][n], ah[mi], b0, b1);
                    mma_bf16(acc[mi][n], ah[mi], c0, c1);
                    mma_bf16(acc[mi][n], al[mi], b0, b1);
                }
        }
        __syncthreads();
    }

    const int r0 = bm * 64 + wm + (lane >> 2);
    const int c0 = bn * 128 + wn + (lane & 3) * 2;
#pragma unroll
    for (int mi = 0; mi < 2; mi++)
#pragma unroll
        for (int n = 0; n < 4; n++) {
            int col = c0 + n * 8;
            float bv0 = bias[col], bv1 = bias[col + 1];
            int row = r0 + mi * 16;
            float2 v0 = {acc[mi][n][0] + bv0, acc[mi][n][1] + bv1};
            float2 v1 = {acc[mi][n][2] + bv0, acc[mi][n][3] + bv1};
            *(float2*)&g_xw[(size_t)row * G4 + col] = v0;
            *(float2*)&g_xw[(size_t)(row + 8) * G4 + col] = v1;
        }
}

// ---------------------------------------------------------------------------
// Activations (fp32)
// ---------------------------------------------------------------------------
__device__ __forceinline__ float sigmoid_f(float x)
{
    float t = __expf(-fabsf(x));
    float inv = 1.0f / (1.0f + t);
    return (x >= 0.0f) ? inv : t * inv;
}

__device__ __forceinline__ float tanh_f(float x)
{
    float e = __expf(-2.0f * fabsf(x));
    float r = (1.0f - e) / (1.0f + e);
    return (x >= 0.0f) ? r : -r;
}

// ---------------------------------------------------------------------------
// Group-split RED barrier: 8 counters (one per K-chunk group of 16 blocks).
// Block b release-REDs counter b>>4 once per step; warp w of every block
// polls counter w (lane 0, relaxed + acquire fence, __syncwarp fan-out).
// ---------------------------------------------------------------------------
__device__ __forceinline__ void cnt_arrive_grp(int grp)
{
    asm volatile("red.release.gpu.global.add.u32 [%0], %1;"
                 :: "l"(&g_cntK[grp * 8]), "r"(1u) : "memory");
}

__device__ __forceinline__ void warp_wait_grp(int grp, int lane, unsigned epoch)
{
    if (lane == 0) {
        const unsigned target = epoch * GRPBLK;
        const unsigned* p = &g_cntK[grp * 8];
        unsigned v;
        do {
            asm volatile("ld.relaxed.gpu.global.u32 %0, [%1];"
                         : "=r"(v) : "l"(p) : "memory");
        } while ((int)(v - target) < 0);
        asm volatile("fence.acq_rel.gpu;" ::: "memory");
    }
    __syncwarp();
}

// ---------------------------------------------------------------------------
// Phase 2: persistent recurrence on tensor cores (R13 + group barriers).
// ---------------------------------------------------------------------------
#define REDS 20   // padded row stride for red (floats)

__global__ void __launch_bounds__(RTHREADS, 1)
lstm_rec_mma(const float* __restrict__ h0,
             const float* __restrict__ Wh,
             float* __restrict__ out)
{
    __shared__ float red[8][32][REDS];   // k-split partials (padded)

    const int tid  = threadIdx.x;
    const int bid  = blockIdx.x;
    const int j0   = bid * JPB;
    const int w    = tid >> 5;    // kg 0..7 — this warp's K-chunk AND wait group
    const int lane = tid & 31;
    const int g    = lane >> 2;
    const int tig  = lane & 3;
    const int mygrp = bid >> 4;   // arrival group of this block

    // ---- one-time: Wh B-fragments in registers (hi/lo), 2 n-tiles ----
    uint2 bh[2][4], bl[2][4];
#pragma unroll
    for (int nt = 0; nt < 2; nt++) {
        int wcol = (g & 3) * 512 + j0 + 2 * nt + (g >> 2);
#pragma unroll
        for (int kt = 0; kt < 4; kt++) {
            int k0 = (4 * w + kt) * 16;
            float w00 = Wh[(size_t)(k0 + 2 * tig) * G4 + wcol];
            float w01 = Wh[(size_t)(k0 + 2 * tig + 1) * G4 + wcol];
            float w10 = Wh[(size_t)(k0 + 8 + 2 * tig) * G4 + wcol];
            float w11 = Wh[(size_t)(k0 + 8 + 2 * tig + 1) * G4 + wcol];
            __nv_bfloat16 h00, h01, h10, h11, l00, l01, l10, l11;
            split1(w00, h00, l00); split1(w01, h01, l01);
            split1(w10, h10, l10); split1(w11, h11, l11);
            bh[nt][kt].x = ((uint32_t)__bfloat16_as_ushort(h01) << 16) |
                           __bfloat16_as_ushort(h00);
            bh[nt][kt].y = ((uint32_t)__bfloat16_as_ushort(h11) << 16) |
                           __bfloat16_as_ushort(h10);
            bl[nt][kt].x = ((uint32_t)__bfloat16_as_ushort(l01) << 16) |
                           __bfloat16_as_ushort(l00);
            bl[nt][kt].y = ((uint32_t)__bfloat16_as_ushort(l11) << 16) |
                           __bfloat16_as_ushort(l10);
        }
    }

    // ---- gate-thread geometry (tid < 128): one h-value (gn, f) each ----
    const int gn  = tid >> 2;
    const int jl  = tid & 3;
    const int f   = j0 + jl;
    const int w_mt   = gn >> 4;
    const int w_r    = gn & 15;
    const int w_ktg  = f >> 4;
    const int w_kc   = f & 15;
    const int w_lane = (w_r & 7) * 4 + ((w_kc & 7) >> 1);
    const int w_reg  = ((w_kc & 8) ? 2 : 0) + ((w_r & 8) ? 1 : 0);
    uint8_t* whi_p = (uint8_t*)&g_hfragHI[0][w_mt][w_ktg][w_lane]
                     + 4 * w_reg + 2 * (f & 1);
    uint8_t* wlo_p = (uint8_t*)&g_hfragLO[0][w_mt][w_ktg][w_lane]
                     + 4 * w_reg + 2 * (f & 1);
    const size_t fragbuf_bytes = sizeof(g_hfragHI[0]);

    float c_st = 0.0f;

    // ---- init h0 fragments (buffer 0), arrive epoch 1 on own group ----
    if (tid < 128) {
        float v = h0[(size_t)gn * HH + f];
        __nv_bfloat16 hb, lb;
        split1(v, hb, lb);
        *(unsigned short*)whi_p = __bfloat16_as_ushort(hb);
        *(unsigned short*)wlo_p = __bfloat16_as_ushort(lb);
    }
    __syncthreads();
    if (tid == 0) cnt_arrive_grp(mygrp);

    // ---- xw mapping (gate threads): 4 scalar loads, one per gate ----
    const size_t xw_row = (size_t)gn * TT * G4 + j0 + jl;

    float xw[4];
    if (tid < 128) {
#pragma unroll
        for (int q = 0; q < 4; q++)
            xw[q] = __ldcg(&g_xw[xw_row + q * 512]);
    }

    for (int t = 0; t < TT; t++) {
        // prefetch next step's xw (independent of sync)
        float nxw[4];
        if (tid < 128) {
            size_t toff = (size_t)((t + 1 < TT) ? t + 1 : t) * G4;
#pragma unroll
            for (int q = 0; q < 4; q++)
                nxw[q] = __ldcg(&g_xw[xw_row + toff + q * 512]);
        }

        // per-warp wait: only this warp's 16 producer blocks must have arrived
        warp_wait_grp(w, lane, (unsigned)(t + 1));

        // load h_t A-fragments
        const int p = t & 1;
        uint4 ahi[2][4], alo[2][4];
#pragma unroll
        for (int mt = 0; mt < 2; mt++)
#pragma unroll
            for (int kt = 0; kt < 4; kt++) {
                ahi[mt][kt] = __ldcg(&g_hfragHI[p][mt][4 * w + kt][lane]);
                alo[mt][kt] = __ldcg(&g_hfragLO[p][mt][4 * w + kt][lane]);
            }

        // split-term MMA, two accumulator sets
        float acc[2][2][4], acl[2][2][4];
#pragma unroll
        for (int mt = 0; mt < 2; mt++)
#pragma unroll
            for (int nt = 0; nt < 2; nt++)
#pragma unroll
                for (int q = 0; q < 4; q++) { acc[mt][nt][q] = 0.0f; acl[mt][nt][q] = 0.0f; }

#pragma unroll
        for (int kt = 0; kt < 4; kt++)
#pragma unroll
            for (int mt = 0; mt < 2; mt++)
#pragma unroll
                for (int nt = 0; nt < 2; nt++) {
                    mma_bf16(acc[mt][nt], (const uint32_t*)&ahi[mt][kt],
                             bh[nt][kt].x, bh[nt][kt].y);
                    mma_bf16(acc[mt][nt], (const uint32_t*)&ahi[mt][kt],
                             bl[nt][kt].x, bl[nt][kt].y);
                    mma_bf16(acl[mt][nt], (const uint32_t*)&alo[mt][kt],
                             bh[nt][kt].x, bh[nt][kt].y);
                }

        // store k-split partials (merge lo-term)
#pragma unroll
        for (int mt = 0; mt < 2; mt++)
#pragma unroll
            for (int nt = 0; nt < 2; nt++) {
                *(float2*)&red[w][mt * 16 + g][nt * 8 + tig * 2] =
                    make_float2(acc[mt][nt][0] + acl[mt][nt][0],
                                acc[mt][nt][1] + acl[mt][nt][1]);
                *(float2*)&red[w][mt * 16 + g + 8][nt * 8 + tig * 2] =
                    make_float2(acc[mt][nt][2] + acl[mt][nt][2],
                                acc[mt][nt][3] + acl[mt][nt][3]);
            }
        __syncthreads();

        // gate threads: float4 reduce + gates + publish h_{t+1}
        float hn;
        if (tid < 128) {
            float s0 = xw[0], s1 = xw[1], s2 = xw[2], s3 = xw[3];
#pragma unroll
            for (int kg = 0; kg < 8; kg++) {
                float4 r = *(const float4*)&red[kg][gn][jl * 4];
                s0 += r.x; s1 += r.y; s2 += r.z; s3 += r.w;
            }

            float gi = sigmoid_f(s0);
            float gf = sigmoid_f(s1);
            float go = sigmoid_f(s2);
            float gg = tanh_f(s3);

            c_st = fmaf(gf, c_st, gi * gg);
            hn = go * tanh_f(c_st);

            __nv_bfloat16 hb, lb;
            split1(hn, hb, lb);
            size_t boff = (size_t)((t + 1) & 1) * fragbuf_bytes;
            *(unsigned short*)(whi_p + boff) = __bfloat16_as_ushort(hb);
            *(unsigned short*)(wlo_p + boff) = __bfloat16_as_ushort(lb);
        }
        // only publishers (warps 0-3) need ordering before the arrive
        asm volatile("bar.sync 1, 128;" ::: "memory");
        if (tid == 0) cnt_arrive_grp(mygrp);   // epoch t+2

        // out store AFTER arrive — off the fence-drain path
        if (tid < 128) {
            out[((size_t)gn * TT + t) * HH + f] = hn;
#pragma unroll
            for (int q = 0; q < 4; q++) xw[q] = nxw[q];
        }
    }
}

// ---------------------------------------------------------------------------
// kernel_launch
// ---------------------------------------------------------------------------
extern "C" void kernel_launch(void* const* d_in, const int* in_sizes, int n_in,
                              void* d_out, int out_size)
{
    const float* x  = (const float*)d_in[0];  // (32, 1024, 512)
    const float* h0 = (const float*)d_in[1];  // (32, 512)
    const float* Wx = (const float*)d_in[2];  // (512, 2048)
    const float* Wh = (const float*)d_in[3];  // (512, 2048)
    const float* b  = (const float*)d_in[4];  // (2048,)
    float* out = (float*)d_out;               // (32, 1024, 512)

    (void)in_sizes; (void)n_in; (void)out_size;

    // zero group counters (in-graph memset node, stream-ordered before kernels)
    void* cnt_ptr = nullptr;
    cudaGetSymbolAddress(&cnt_ptr, g_cntK);
    cudaMemsetAsync(cnt_ptr, 0, sizeof(unsigned) * 8 * 8);

    // Phase 1: split Wx, then fused-convert tensor-core GEMM (x read as fp32)
    size_t nw4 = (size_t)DD * G4 / 4;
    split_kernel_w<<<(unsigned)((nw4 + 255) / 256), 256>>>(Wx);

    dim3 g1(G4 / 128, MROWS / 64);  // (16, 512)
    gemm_xw_mma<<<g1, 256>>>(x, b);

    // Phase 2: persistent tensor-core recurrence
    lstm_rec_mma<<<RBLOCKS, RTHREADS>>>(h0, Wh, out);
}

// round 15
// speedup vs baseline: 1.2306x; 1.2306x over previous
#include <cuda_runtime.h>
#include <cuda_bf16.h>
#include <math.h>
#include <stdint.h>

// Problem constants
#define NB 32            // batch
#define TT 1024          // timesteps
#define DD 512           // input dim
#define HH 512           // hidden dim
#define G4 2048          // 4*H
#define MROWS (NB * TT)  // 32768

// Recurrent kernel config: 2 independent batch groups of 64 blocks
#define RBLOCKS 128
#define RTHREADS 256
#define BPG 64           // blocks per group
#define NBG 16           // batches per group
#define JPB 8            // h-columns per block (64*8 = 512)

// Scratch (device globals; no cudaMalloc allowed)
__device__ float g_xw[(size_t)MROWS * G4];   // 268 MB: x @ Wx + b
__device__ unsigned g_cntG[2 * 8];           // per-group counters, 32B apart

// h exchanged in MMA A-fragment layout: [buf][grp][ktile][lane] -> uint4 (m16)
__device__ uint4 g_hfragHI[2][2][32][32];
__device__ uint4 g_hfragLO[2][2][32][32];

// bf16 hi/lo split buffers for Wx only (x is converted in-GEMM)
__device__ __nv_bfloat16 g_whi[(size_t)DD * G4];
__device__ __nv_bfloat16 g_wlo[(size_t)DD * G4];

// ---------------------------------------------------------------------------
// fp32 -> bf16 hi + lo split
// ---------------------------------------------------------------------------
__device__ __forceinline__ void split1(float v, __nv_bfloat16& h, __nv_bfloat16& l)
{
    h = __float2bfloat16(v);
    l = __float2bfloat16(v - __bfloat162float(h));
}

__device__ __forceinline__ void split8_pack(const float* v, uint4& hi, uint4& lo)
{
    unsigned h[8], l[8];
#pragma unroll
    for (int i = 0; i < 8; i++) {
        __nv_bfloat16 hb, lb;
        split1(v[i], hb, lb);
        h[i] = __bfloat16_as_ushort(hb);
        l[i] = __bfloat16_as_ushort(lb);
    }
    hi.x = (h[1] << 16) | h[0]; hi.y = (h[3] << 16) | h[2];
    hi.z = (h[5] << 16) | h[4]; hi.w = (h[7] << 16) | h[6];
    lo.x = (l[1] << 16) | l[0]; lo.y = (l[3] << 16) | l[2];
    lo.z = (l[5] << 16) | l[4]; lo.w = (l[7] << 16) | l[6];
}

__global__ void __launch_bounds__(256) split_kernel_w(const float* __restrict__ src)
{
    size_t i = (size_t)blockIdx.x * blockDim.x + threadIdx.x;
    size_t n4 = (size_t)DD * G4 / 4;
    if (i >= n4) return;
    float4 v = ((const float4*)src)[i];
    __nv_bfloat16 h0, h1, h2, h3, l0, l1, l2, l3;
    split1(v.x, h0, l0); split1(v.y, h1, l1);
    split1(v.z, h2, l2); split1(v.w, h3, l3);
    ((__nv_bfloat162*)g_whi)[2 * i]     = __nv_bfloat162(h0, h1);
    ((__nv_bfloat162*)g_whi)[2 * i + 1] = __nv_bfloat162(h2, h3);
    ((__nv_bfloat162*)g_wlo)[2 * i]     = __nv_bfloat162(l0, l1);
    ((__nv_bfloat162*)g_wlo)[2 * i + 1] = __nv_bfloat162(l2, l3);
}

// ---------------------------------------------------------------------------
// PTX wrappers
// ---------------------------------------------------------------------------
__device__ __forceinline__ void ldsm_x4(uint32_t& r0, uint32_t& r1, uint32_t& r2,
                                        uint32_t& r3, const void* p)
{
    uint32_t a = (uint32_t)__cvta_generic_to_shared(p);
    asm volatile("ldmatrix.sync.aligned.m8n8.x4.shared.b16 {%0,%1,%2,%3}, [%4];"
                 : "=r"(r0), "=r"(r1), "=r"(r2), "=r"(r3) : "r"(a));
}

__device__ __forceinline__ void ldsm_x4_t(uint32_t& r0, uint32_t& r1, uint32_t& r2,
                                          uint32_t& r3, const void* p)
{
    uint32_t a = (uint32_t)__cvta_generic_to_shared(p);
    asm volatile("ldmatrix.sync.aligned.m8n8.x4.trans.shared.b16 {%0,%1,%2,%3}, [%4];"
                 : "=r"(r0), "=r"(r1), "=r"(r2), "=r"(r3) : "r"(a));
}

__device__ __forceinline__ void mma_bf16(float* c, const uint32_t* a,
                                         uint32_t b0, uint32_t b1)
{
    asm volatile(
        "mma.sync.aligned.m16n8k16.row.col.f32.bf16.bf16.f32 "
        "{%0,%1,%2,%3},{%4,%5,%6,%7},{%8,%9},{%0,%1,%2,%3};"
        : "+f"(c[0]), "+f"(c[1]), "+f"(c[2]), "+f"(c[3])
        : "r"(a[0]), "r"(a[1]), "r"(a[2]), "r"(a[3]), "r"(b0), "r"(b1));
}

// ---------------------------------------------------------------------------
// Phase 1 GEMM (R13, measured best): bf16 split, BM=64 x BN=128 x BK=32,
// 2 blocks/SM, register double-buffered loads; x converted IN-KERNEL.
// ---------------------------------------------------------------------------
#define P1_SA 40
#define P1_SB 136

__global__ void __launch_bounds__(256, 2) gemm_xw_mma(const float* __restrict__ x,
                                                      const float* __restrict__ bias)
{
    __shared__ __nv_bfloat16 Ah[64 * P1_SA];
    __shared__ __nv_bfloat16 Al[64 * P1_SA];
    __shared__ __nv_bfloat16 Bh[32 * P1_SB];
    __shared__ __nv_bfloat16 Bl[32 * P1_SB];

    const int tid = threadIdx.x;
    const int bn = blockIdx.x;
    const int bm = blockIdx.y;
    const int warp = tid >> 5;
    const int lane = tid & 31;
    const int wm = (warp >> 2) * 32;
    const int wn = (warp & 3) * 32;

    const int arow = tid >> 2;
    const int acol = (tid & 3) * 8;
    const int brow = tid >> 4;
    const int bcol = (tid & 15) * 8;

    const size_t a_off = (size_t)(bm * 64 + arow) * DD + acol;
    const size_t b_off0 = (size_t)brow * G4 + bn * 128 + bcol;

    float acc[2][4][4];
#pragma unroll
    for (int mi = 0; mi < 2; mi++)
#pragma unroll
        for (int n = 0; n < 4; n++)
#pragma unroll
            for (int q = 0; q < 4; q++) acc[mi][n][q] = 0.0f;

    const int a_lrow = lane & 15;
    const int a_lcol = (lane >> 4) << 3;

    float4 rx0 = *(const float4*)&x[a_off];
    float4 rx1 = *(const float4*)&x[a_off + 4];
    uint4 rb_h[2], rb_l[2];
#pragma unroll
    for (int i = 0; i < 2; i++) {
        size_t go = b_off0 + (size_t)(i * 16) * G4;
        rb_h[i] = *(const uint4*)&g_whi[go];
        rb_l[i] = *(const uint4*)&g_wlo[go];
    }

    for (int k0 = 0; k0 < DD; k0 += 32) {
        {
            float xv[8] = {rx0.x, rx0.y, rx0.z, rx0.w, rx1.x, rx1.y, rx1.z, rx1.w};
            uint4 ah4, al4;
            split8_pack(xv, ah4, al4);
            *(uint4*)&Ah[arow * P1_SA + acol] = ah4;
            *(uint4*)&Al[arow * P1_SA + acol] = al4;
        }
#pragma unroll
        for (int i = 0; i < 2; i++) {
            *(uint4*)&Bh[(brow + i * 16) * P1_SB + bcol] = rb_h[i];
            *(uint4*)&Bl[(brow + i * 16) * P1_SB + bcol] = rb_l[i];
        }
        __syncthreads();

        if (k0 + 32 < DD) {
            rx0 = *(const float4*)&x[a_off + k0 + 32];
            rx1 = *(const float4*)&x[a_off + k0 + 36];
#pragma unroll
            for (int i = 0; i < 2; i++) {
                size_t go = b_off0 + (size_t)(k0 + 32 + i * 16) * G4;
                rb_h[i] = *(const uint4*)&g_whi[go];
                rb_l[i] = *(const uint4*)&g_wlo[go];
            }
        }

#pragma unroll
        for (int kk = 0; kk < 32; kk += 16) {
            uint32_t ah[2][4], al[2][4], bh[2][4], bl[2][4];
#pragma unroll
            for (int mi = 0; mi < 2; mi++) {
                const __nv_bfloat16* pa =
                    &Ah[(wm + mi * 16 + a_lrow) * P1_SA + kk + a_lcol];
                ldsm_x4(ah[mi][0], ah[mi][1], ah[mi][2], ah[mi][3], pa);
                const __nv_bfloat16* pl =
                    &Al[(wm + mi * 16 + a_lrow) * P1_SA + kk + a_lcol];
                ldsm_x4(al[mi][0], al[mi][1], al[mi][2], al[mi][3], pl);
            }
#pragma unroll
            for (int g = 0; g < 2; g++) {
                const __nv_bfloat16* pb =
                    &Bh[(kk + a_lrow) * P1_SB + wn + g * 16 + a_lcol];
                ldsm_x4_t(bh[g][0], bh[g][1], bh[g][2], bh[g][3], pb);
                const __nv_bfloat16* pbl =
                    &Bl[(kk + a_lrow) * P1_SB + wn + g * 16 + a_lcol];
                ldsm_x4_t(bl[g][0], bl[g][1], bl[g][2], bl[g][3], pbl);
            }
#pragma unroll
            for (int mi = 0; mi < 2; mi++)
#pragma unroll
                for (int n = 0; n < 4; n++) {
                    uint32_t b0 = bh[n >> 1][(n & 1) * 2];
                    uint32_t b1 = bh[n >> 1][(n & 1) * 2 + 1];
                    uint32_t c0 = bl[n >> 1][(n & 1) * 2];
                    uint32_t c1 = bl[n >> 1][(n & 1) * 2 + 1];
                    mma_bf16(acc[mi][n], ah[mi], b0, b1);
                    mma_bf16(acc[mi][n], ah[mi], c0, c1);
                    mma_bf16(acc[mi][n], al[mi], b0, b1);
                }
        }
        __syncthreads();
    }

    const int r0 = bm * 64 + wm + (lane >> 2);
    const int c0 = bn * 128 + wn + (lane & 3) * 2;
#pragma unroll
    for (int mi = 0; mi < 2; mi++)
#pragma unroll
        for (int n = 0; n < 4; n++) {
            int col = c0 + n * 8;
            float bv0 = bias[col], bv1 = bias[col + 1];
            int row = r0 + mi * 16;
            float2 v0 = {acc[mi][n][0] + bv0, acc[mi][n][1] + bv1};
            float2 v1 = {acc[mi][n][2] + bv0, acc[mi][n][3] + bv1};
            *(float2*)&g_xw[(size_t)row * G4 + col] = v0;
            *(float2*)&g_xw[(size_t)(row + 8) * G4 + col] = v1;
        }
}

// ---------------------------------------------------------------------------
// Activations (fp32)
// ---------------------------------------------------------------------------
__device__ __forceinline__ float sigmoid_f(float x)
{
    float t = __expf(-fabsf(x));
    float inv = 1.0f / (1.0f + t);
    return (x >= 0.0f) ? inv : t * inv;
}

__device__ __forceinline__ float tanh_f(float x)
{
    float e = __expf(-2.0f * fabsf(x));
    float r = (1.0f - e) / (1.0f + e);
    return (x >= 0.0f) ? r : -r;
}

// ---------------------------------------------------------------------------
// Per-group counter barrier: arrive = release-reduction on own group counter;
// detection by dual pollers sharing a monotonic smem epoch flag (R13 proven).
// ---------------------------------------------------------------------------
__device__ __forceinline__ void cnt_arrive_g(int grp)
{
    asm volatile("red.release.gpu.global.add.u32 [%0], %1;"
                 :: "l"(&g_cntG[grp * 8]), "r"(1u) : "memory");
}

__device__ __forceinline__ void cnt_wait_dual_g(int grp, volatile unsigned* s_done,
                                                unsigned k)
{
    const unsigned target = k * BPG;
    const unsigned* p = &g_cntG[grp * 8];
    unsigned v, d;
    do {
        asm volatile("ld.relaxed.gpu.global.u32 %0, [%1];"
                     : "=r"(v) : "l"(p) : "memory");
        d = *s_done;
        if ((int)(v - target) >= 0) { *s_done = k; d = k; }
    } while ((int)(d - k) < 0);
    asm volatile("fence.acq_rel.gpu;" ::: "memory");
}

// ---------------------------------------------------------------------------
// Phase 2: persistent recurrence, 2 INDEPENDENT batch groups of 64 blocks.
// Group grp = bid>>6 owns batches [16*grp, 16*grp+16). Block owns 8 h-cols
// (j0 = (bid&63)*8) = 32 gate cols packed c = jl*4 + gate. Warp w = K-chunk
// [64w, 64w+64): 1 m16-tile x 4 n8-tiles x 4 ktiles x 3 terms = 48 MMA.
// ---------------------------------------------------------------------------
#define REDS 36   // padded row stride for red (floats)

__global__ void __launch_bounds__(RTHREADS, 1)
lstm_rec_mma(const float* __restrict__ h0,
             const float* __restrict__ Wh,
             float* __restrict__ out)
{
    __shared__ float red[8][16][REDS];   // k-split partials (padded)
    __shared__ unsigned s_done;          // monotonic completed-epoch flag

    const int tid  = threadIdx.x;
    const int bid  = blockIdx.x;
    const int grp  = bid >> 6;          // batch group 0/1
    const int lb   = bid & 63;          // local block in group
    const int j0   = lb * JPB;          // 8 h-cols
    const int w    = tid >> 5;          // K-chunk 0..7
    const int lane = tid & 31;
    const int g    = lane >> 2;         // 0..7
    const int tig  = lane & 3;          // 0..3

    // ---- one-time: Wh B-fragments in registers (hi/lo), 4 n-tiles ----
    // packed col c = nt*8 + g = jl*4 + gate  =>  gate = g&3, jl = 2*nt + (g>>2)
    uint2 bh[4][4], bl[4][4];
#pragma unroll
    for (int nt = 0; nt < 4; nt++) {
        int wcol = (g & 3) * 512 + j0 + 2 * nt + (g >> 2);
#pragma unroll
        for (int kt = 0; kt < 4; kt++) {
            int k0 = (4 * w + kt) * 16;
            float w00 = Wh[(size_t)(k0 + 2 * tig) * G4 + wcol];
            float w01 = Wh[(size_t)(k0 + 2 * tig + 1) * G4 + wcol];
            float w10 = Wh[(size_t)(k0 + 8 + 2 * tig) * G4 + wcol];
            float w11 = Wh[(size_t)(k0 + 8 + 2 * tig + 1) * G4 + wcol];
            __nv_bfloat16 h00, h01, h10, h11, l00, l01, l10, l11;
            split1(w00, h00, l00); split1(w01, h01, l01);
            split1(w10, h10, l10); split1(w11, h11, l11);
            bh[nt][kt].x = ((uint32_t)__bfloat16_as_ushort(h01) << 16) |
                           __bfloat16_as_ushort(h00);
            bh[nt][kt].y = ((uint32_t)__bfloat16_as_ushort(h11) << 16) |
                           __bfloat16_as_ushort(h10);
            bl[nt][kt].x = ((uint32_t)__bfloat16_as_ushort(l01) << 16) |
                           __bfloat16_as_ushort(l00);
            bl[nt][kt].y = ((uint32_t)__bfloat16_as_ushort(l11) << 16) |
                           __bfloat16_as_ushort(l10);
        }
    }

    // ---- gate-thread geometry (tid < 128): one h-value (gn, f) each ----
    const int gn  = tid >> 3;           // local batch row 0..15
    const int jl  = tid & 7;            // 0..7
    const int f   = j0 + jl;            // global h column
    const int nglob = grp * NBG + gn;   // global batch row
    const int w_r    = gn;              // m16 row
    const int w_ktg  = f >> 4;
    const int w_kc   = f & 15;
    const int w_lane = (w_r & 7) * 4 + ((w_kc & 7) >> 1);
    const int w_reg  = ((w_kc & 8) ? 2 : 0) + ((w_r & 8) ? 1 : 0);
    uint8_t* whi_p = (uint8_t*)&g_hfragHI[0][grp][w_ktg][w_lane]
                     + 4 * w_reg + 2 * (f & 1);
    uint8_t* wlo_p = (uint8_t*)&g_hfragLO[0][grp][w_ktg][w_lane]
                     + 4 * w_reg + 2 * (f & 1);
    const size_t fragbuf_bytes = sizeof(g_hfragHI[0]);  // stride buf0 -> buf1

    float c_st = 0.0f;

    // ---- init h0 fragments (buffer 0), arrive epoch 1 on own group ----
    if (tid == 0) s_done = 0u;
    if (tid < 128) {
        float v = h0[(size_t)nglob * HH + f];
        __nv_bfloat16 hb, lb2;
        split1(v, hb, lb2);
        *(unsigned short*)whi_p = __bfloat16_as_ushort(hb);
        *(unsigned short*)wlo_p = __bfloat16_as_ushort(lb2);
    }
    __syncthreads();
    if (tid == 0) cnt_arrive_g(grp);

    // ---- xw mapping (gate threads): 4 scalar loads, one per gate ----
    const size_t xw_row = (size_t)nglob * TT * G4 + j0 + jl;

    float xw[4];
    if (tid < 128) {
#pragma unroll
        for (int q = 0; q < 4; q++)
            xw[q] = __ldcg(&g_xw[xw_row + q * 512]);
    }

    for (int t = 0; t < TT; t++) {
        // prefetch next step's xw (independent of sync)
        float nxw[4];
        if (tid < 128) {
            size_t toff = (size_t)((t + 1 < TT) ? t + 1 : t) * G4;
#pragma unroll
            for (int q = 0; q < 4; q++)
                nxw[q] = __ldcg(&g_xw[xw_row + toff + q * 512]);
        }

        // wait for own group's h_t: dual pollers, smem epoch fan-in
        if (tid == 0 || tid == 128) cnt_wait_dual_g(grp, &s_done, (unsigned)(t + 1));
        __syncthreads();

        // load h_t A-fragments (m16: single tile per ktile)
        const int p = t & 1;
        uint4 ahi[4], alo[4];
#pragma unroll
        for (int kt = 0; kt < 4; kt++) {
            ahi[kt] = __ldcg(&g_hfragHI[p][grp][4 * w + kt][lane]);
            alo[kt] = __ldcg(&g_hfragLO[p][grp][4 * w + kt][lane]);
        }

        // split-term MMA, two accumulator sets
        float acc[4][4], acl[4][4];
#pragma unroll
        for (int nt = 0; nt < 4; nt++)
#pragma unroll
            for (int q = 0; q < 4; q++) { acc[nt][q] = 0.0f; acl[nt][q] = 0.0f; }

#pragma unroll
        for (int kt = 0; kt < 4; kt++)
#pragma unroll
            for (int nt = 0; nt < 4; nt++) {
                mma_bf16(acc[nt], (const uint32_t*)&ahi[kt],
                         bh[nt][kt].x, bh[nt][kt].y);
                mma_bf16(acc[nt], (const uint32_t*)&ahi[kt],
                         bl[nt][kt].x, bl[nt][kt].y);
                mma_bf16(acl[nt], (const uint32_t*)&alo[kt],
                         bh[nt][kt].x, bh[nt][kt].y);
            }

        // store k-split partials (merge lo-term); D rows g and g+8
#pragma unroll
        for (int nt = 0; nt < 4; nt++) {
            *(float2*)&red[w][g][nt * 8 + tig * 2] =
                make_float2(acc[nt][0] + acl[nt][0], acc[nt][1] + acl[nt][1]);
            *(float2*)&red[w][g + 8][nt * 8 + tig * 2] =
                make_float2(acc[nt][2] + acl[nt][2], acc[nt][3] + acl[nt][3]);
        }
        __syncthreads();

        // gate threads: float4 reduce + gates + publish h_{t+1}
        float hn;
        if (tid < 128) {
            float s0 = xw[0], s1 = xw[1], s2 = xw[2], s3 = xw[3];
#pragma unroll
            for (int kg = 0; kg < 8; kg++) {
                float4 r = *(const float4*)&red[kg][gn][jl * 4];
                s0 += r.x; s1 += r.y; s2 += r.z; s3 += r.w;
            }

            float gi = sigmoid_f(s0);
            float gf = sigmoid_f(s1);
            float go = sigmoid_f(s2);
            float gg = tanh_f(s3);

            c_st = fmaf(gf, c_st, gi * gg);
            hn = go * tanh_f(c_st);

            __nv_bfloat16 hb, lb2;
            split1(hn, hb, lb2);
            size_t boff = (size_t)((t + 1) & 1) * fragbuf_bytes;
            *(unsigned short*)(whi_p + boff) = __bfloat16_as_ushort(hb);
            *(unsigned short*)(wlo_p + boff) = __bfloat16_as_ushort(lb2);
        }
        // only publishers (warps 0-3) need ordering before the arrive
        asm volatile("bar.sync 1, 128;" ::: "memory");
        if (tid == 0) cnt_arrive_g(grp);   // epoch t+2

        // out store AFTER arrive — off the fence-drain path
        if (tid < 128) {
            out[((size_t)nglob * TT + t) * HH + f] = hn;
#pragma unroll
            for (int q = 0; q < 4; q++) xw[q] = nxw[q];
        }
    }
}

// ---------------------------------------------------------------------------
// kernel_launch
// ---------------------------------------------------------------------------
extern "C" void kernel_launch(void* const* d_in, const int* in_sizes, int n_in,
                              void* d_out, int out_size)
{
    const float* x  = (const float*)d_in[0];  // (32, 1024, 512)
    const float* h0 = (const float*)d_in[1];  // (32, 512)
    const float* Wx = (const float*)d_in[2];  // (512, 2048)
    const float* Wh = (const float*)d_in[3];  // (512, 2048)
    const float* b  = (const float*)d_in[4];  // (2048,)
    float* out = (float*)d_out;               // (32, 1024, 512)

    (void)in_sizes; (void)n_in; (void)out_size;

    // zero group counters (in-graph memset node, stream-ordered before kernels)
    void* cnt_ptr = nullptr;
    cudaGetSymbolAddress(&cnt_ptr, g_cntG);
    cudaMemsetAsync(cnt_ptr, 0, sizeof(unsigned) * 2 * 8);

    // Phase 1: split Wx, then fused-convert tensor-core GEMM (x read as fp32)
    size_t nw4 = (size_t)DD * G4 / 4;
    split_kernel_w<<<(unsigned)((nw4 + 255) / 256), 256>>>(Wx);

    dim3 g1(G4 / 128, MROWS / 64);  // (16, 512)
    gemm_xw_mma<<<g1, 256>>>(x, b);

    // Phase 2: persistent tensor-core recurrence, 2 independent batch groups
    lstm_rec_mma<<<RBLOCKS, RTHREADS>>>(h0, Wh, out);
}

// round 16
// speedup vs baseline: 1.2486x; 1.0146x over previous
#include <cuda_runtime.h>
#include <cuda_bf16.h>
#include <math.h>
#include <stdint.h>

// Problem constants
#define NB 32            // batch
#define TT 1024          // timesteps
#define DD 512           // input dim
#define HH 512           // hidden dim
#define G4 2048          // 4*H
#define MROWS (NB * TT)  // 32768

// Recurrent kernel config: 2 independent batch groups of 64 blocks
#define RBLOCKS 128
#define RTHREADS 256
#define BPG 64           // blocks per group
#define NBG 16           // batches per group
#define JPB 8            // h-columns per block (64*8 = 512)

// Scratch (device globals; no cudaMalloc allowed)
__device__ float g_xw[(size_t)MROWS * G4];   // 268 MB: x @ Wx + b
__device__ unsigned g_cntG[2 * 8];           // per-group counters, 32B apart

// h exchanged in MMA A-fragment layout: [buf][grp][ktile][lane] -> uint4 (m16)
__device__ uint4 g_hfragHI[2][2][32][32];
__device__ uint4 g_hfragLO[2][2][32][32];

// bf16 hi/lo split buffers for Wx only (x is converted in-GEMM)
__device__ __nv_bfloat16 g_whi[(size_t)DD * G4];
__device__ __nv_bfloat16 g_wlo[(size_t)DD * G4];

// ---------------------------------------------------------------------------
// fp32 -> bf16 hi + lo split
// ---------------------------------------------------------------------------
__device__ __forceinline__ void split1(float v, __nv_bfloat16& h, __nv_bfloat16& l)
{
    h = __float2bfloat16(v);
    l = __float2bfloat16(v - __bfloat162float(h));
}

__device__ __forceinline__ void split8_pack(const float* v, uint4& hi, uint4& lo)
{
    unsigned h[8], l[8];
#pragma unroll
    for (int i = 0; i < 8; i++) {
        __nv_bfloat16 hb, lb;
        split1(v[i], hb, lb);
        h[i] = __bfloat16_as_ushort(hb);
        l[i] = __bfloat16_as_ushort(lb);
    }
    hi.x = (h[1] << 16) | h[0]; hi.y = (h[3] << 16) | h[2];
    hi.z = (h[5] << 16) | h[4]; hi.w = (h[7] << 16) | h[6];
    lo.x = (l[1] << 16) | l[0]; lo.y = (l[3] << 16) | l[2];
    lo.z = (l[5] << 16) | l[4]; lo.w = (l[7] << 16) | l[6];
}

__global__ void __launch_bounds__(256) split_kernel_w(const float* __restrict__ src)
{
    size_t i = (size_t)blockIdx.x * blockDim.x + threadIdx.x;
    size_t n4 = (size_t)DD * G4 / 4;
    if (i >= n4) return;
    float4 v = ((const float4*)src)[i];
    __nv_bfloat16 h0, h1, h2, h3, l0, l1, l2, l3;
    split1(v.x, h0, l0); split1(v.y, h1, l1);
    split1(v.z, h2, l2); split1(v.w, h3, l3);
    ((__nv_bfloat162*)g_whi)[2 * i]     = __nv_bfloat162(h0, h1);
    ((__nv_bfloat162*)g_whi)[2 * i + 1] = __nv_bfloat162(h2, h3);
    ((__nv_bfloat162*)g_wlo)[2 * i]     = __nv_bfloat162(l0, l1);
    ((__nv_bfloat162*)g_wlo)[2 * i + 1] = __nv_bfloat162(l2, l3);
}

// ---------------------------------------------------------------------------
// PTX wrappers
// ---------------------------------------------------------------------------
__device__ __forceinline__ void ldsm_x4(uint32_t& r0, uint32_t& r1, uint32_t& r2,
                                        uint32_t& r3, const void* p)
{
    uint32_t a = (uint32_t)__cvta_generic_to_shared(p);
    asm volatile("ldmatrix.sync.aligned.m8n8.x4.shared.b16 {%0,%1,%2,%3}, [%4];"
                 : "=r"(r0), "=r"(r1), "=r"(r2), "=r"(r3) : "r"(a));
}

__device__ __forceinline__ void ldsm_x4_t(uint32_t& r0, uint32_t& r1, uint32_t& r2,
                                          uint32_t& r3, const void* p)
{
    uint32_t a = (uint32_t)__cvta_generic_to_shared(p);
    asm volatile("ldmatrix.sync.aligned.m8n8.x4.trans.shared.b16 {%0,%1,%2,%3}, [%4];"
                 : "=r"(r0), "=r"(r1), "=r"(r2), "=r"(r3) : "r"(a));
}

__device__ __forceinline__ void mma_bf16(float* c, const uint32_t* a,
                                         uint32_t b0, uint32_t b1)
{
    asm volatile(
        "mma.sync.aligned.m16n8k16.row.col.f32.bf16.bf16.f32 "
        "{%0,%1,%2,%3},{%4,%5,%6,%7},{%8,%9},{%0,%1,%2,%3};"
        : "+f"(c[0]), "+f"(c[1]), "+f"(c[2]), "+f"(c[3])
        : "r"(a[0]), "r"(a[1]), "r"(a[2]), "r"(a[3]), "r"(b0), "r"(b1));
}

// ---------------------------------------------------------------------------
// Phase 1 GEMM (R13, measured best): bf16 split, BM=64 x BN=128 x BK=32,
// 2 blocks/SM, register double-buffered loads; x converted IN-KERNEL.
// ---------------------------------------------------------------------------
#define P1_SA 40
#define P1_SB 136

__global__ void __launch_bounds__(256, 2) gemm_xw_mma(const float* __restrict__ x,
                                                      const float* __restrict__ bias)
{
    __shared__ __nv_bfloat16 Ah[64 * P1_SA];
    __shared__ __nv_bfloat16 Al[64 * P1_SA];
    __shared__ __nv_bfloat16 Bh[32 * P1_SB];
    __shared__ __nv_bfloat16 Bl[32 * P1_SB];

    const int tid = threadIdx.x;
    const int bn = blockIdx.x;
    const int bm = blockIdx.y;
    const int warp = tid >> 5;
    const int lane = tid & 31;
    const int wm = (warp >> 2) * 32;
    const int wn = (warp & 3) * 32;

    const int arow = tid >> 2;
    const int acol = (tid & 3) * 8;
    const int brow = tid >> 4;
    const int bcol = (tid & 15) * 8;

    const size_t a_off = (size_t)(bm * 64 + arow) * DD + acol;
    const size_t b_off0 = (size_t)brow * G4 + bn * 128 + bcol;

    float acc[2][4][4];
#pragma unroll
    for (int mi = 0; mi < 2; mi++)
#pragma unroll
        for (int n = 0; n < 4; n++)
#pragma unroll
            for (int q = 0; q < 4; q++) acc[mi][n][q] = 0.0f;

    const int a_lrow = lane & 15;
    const int a_lcol = (lane >> 4) << 3;

    float4 rx0 = *(const float4*)&x[a_off];
    float4 rx1 = *(const float4*)&x[a_off + 4];
    uint4 rb_h[2], rb_l[2];
#pragma unroll
    for (int i = 0; i < 2; i++) {
        size_t go = b_off0 + (size_t)(i * 16) * G4;
        rb_h[i] = *(const uint4*)&g_whi[go];
        rb_l[i] = *(const uint4*)&g_wlo[go];
    }

    for (int k0 = 0; k0 < DD; k0 += 32) {
        {
            float xv[8] = {rx0.x, rx0.y, rx0.z, rx0.w, rx1.x, rx1.y, rx1.z, rx1.w};
            uint4 ah4, al4;
            split8_pack(xv, ah4, al4);
            *(uint4*)&Ah[arow * P1_SA + acol] = ah4;
            *(uint4*)&Al[arow * P1_SA + acol] = al4;
        }
#pragma unroll
        for (int i = 0; i < 2; i++) {
            *(uint4*)&Bh[(brow + i * 16) * P1_SB + bcol] = rb_h[i];
            *(uint4*)&Bl[(brow + i * 16) * P1_SB + bcol] = rb_l[i];
        }
        __syncthreads();

        if (k0 + 32 < DD) {
            rx0 = *(const float4*)&x[a_off + k0 + 32];
            rx1 = *(const float4*)&x[a_off + k0 + 36];
#pragma unroll
            for (int i = 0; i < 2; i++) {
                size_t go = b_off0 + (size_t)(k0 + 32 + i * 16) * G4;
                rb_h[i] = *(const uint4*)&g_whi[go];
                rb_l[i] = *(const uint4*)&g_wlo[go];
            }
        }

#pragma unroll
        for (int kk = 0; kk < 32; kk += 16) {
            uint32_t ah[2][4], al[2][4], bh[2][4], bl[2][4];
#pragma unroll
            for (int mi = 0; mi < 2; mi++) {
                const __nv_bfloat16* pa =
                    &Ah[(wm + mi * 16 + a_lrow) * P1_SA + kk + a_lcol];
                ldsm_x4(ah[mi][0], ah[mi][1], ah[mi][2], ah[mi][3], pa);
                const __nv_bfloat16* pl =
                    &Al[(wm + mi * 16 + a_lrow) * P1_SA + kk + a_lcol];
                ldsm_x4(al[mi][0], al[mi][1], al[mi][2], al[mi][3], pl);
            }
#pragma unroll
            for (int g = 0; g < 2; g++) {
                const __nv_bfloat16* pb =
                    &Bh[(kk + a_lrow) * P1_SB + wn + g * 16 + a_lcol];
                ldsm_x4_t(bh[g][0], bh[g][1], bh[g][2], bh[g][3], pb);
                const __nv_bfloat16* pbl =
                    &Bl[(kk + a_lrow) * P1_SB + wn + g * 16 + a_lcol];
                ldsm_x4_t(bl[g][0], bl[g][1], bl[g][2], bl[g][3], pbl);
            }
#pragma unroll
            for (int mi = 0; mi < 2; mi++)
#pragma unroll
                for (int n = 0; n < 4; n++) {
                    uint32_t b0 = bh[n >> 1][(n & 1) * 2];
                    uint32_t b1 = bh[n >> 1][(n & 1) * 2 + 1];
                    uint32_t c0 = bl[n >> 1][(n & 1) * 2];
                    uint32_t c1 = bl[n >> 1][(n & 1) * 2 + 1];
                    mma_bf16(acc[mi][n], ah[mi], b0, b1);
                    mma_bf16(acc[mi][n], ah[mi], c0, c1);
                    mma_bf16(acc[mi][n], al[mi], b0, b1);
                }
        }
        __syncthreads();
    }

    const int r0 = bm * 64 + wm + (lane >> 2);
    const int c0 = bn * 128 + wn + (lane & 3) * 2;
#pragma unroll
    for (int mi = 0; mi < 2; mi++)
#pragma unroll
        for (int n = 0; n < 4; n++) {
            int col = c0 + n * 8;
            float bv0 = bias[col], bv1 = bias[col + 1];
            int row = r0 + mi * 16;
            float2 v0 = {acc[mi][n][0] + bv0, acc[mi][n][1] + bv1};
            float2 v1 = {acc[mi][n][2] + bv0, acc[mi][n][3] + bv1};
            *(float2*)&g_xw[(size_t)row * G4 + col] = v0;
            *(float2*)&g_xw[(size_t)(row + 8) * G4 + col] = v1;
        }
}

// ---------------------------------------------------------------------------
// Activations (fp32)
// ---------------------------------------------------------------------------
__device__ __forceinline__ float sigmoid_f(float x)
{
    float t = __expf(-fabsf(x));
    float inv = 1.0f / (1.0f + t);
    return (x >= 0.0f) ? inv : t * inv;
}

__device__ __forceinline__ float tanh_f(float x)
{
    float e = __expf(-2.0f * fabsf(x));
    float r = (1.0f - e) / (1.0f + e);
    return (x >= 0.0f) ? r : -r;
}

// ---------------------------------------------------------------------------
// Per-group counter barrier: arrive = release-reduction on own group counter;
// dual global pollers set a monotonic smem epoch flag; all other warps spin
// on the smem flag (LDS-local, zero L2 traffic) and start immediately.
// ---------------------------------------------------------------------------
__device__ __forceinline__ void cnt_arrive_g(int grp)
{
    asm volatile("red.release.gpu.global.add.u32 [%0], %1;"
                 :: "l"(&g_cntG[grp * 8]), "r"(1u) : "memory");
}

__device__ __forceinline__ void cnt_wait_dual_g(int grp, volatile unsigned* s_done,
                                                unsigned k)
{
    const unsigned target = k * BPG;
    const unsigned* p = &g_cntG[grp * 8];
    unsigned v, d;
    do {
        asm volatile("ld.relaxed.gpu.global.u32 %0, [%1];"
                     : "=r"(v) : "l"(p) : "memory");
        d = *s_done;
        if ((int)(v - target) >= 0) { *s_done = k; d = k; }
    } while ((int)(d - k) < 0);
    asm volatile("fence.acq_rel.gpu;" ::: "memory");
}

// ---------------------------------------------------------------------------
// Phase 2: persistent recurrence, 2 INDEPENDENT batch groups of 64 blocks.
// Group grp = bid>>6 owns batches [16*grp, 16*grp+16). Block owns 8 h-cols
// (j0 = (bid&63)*8) = 32 gate cols packed c = jl*4 + gate. Warp w = K-chunk
// [64w, 64w+64): 1 m16-tile x 4 n8-tiles x 4 ktiles x 3 terms = 48 MMA.
// Wait fan-out via smem flag spin (no block-wide barrier on the wait side).
// ---------------------------------------------------------------------------
#define REDS 36   // padded row stride for red (floats)

__global__ void __launch_bounds__(RTHREADS, 1)
lstm_rec_mma(const float* __restrict__ h0,
             const float* __restrict__ Wh,
             float* __restrict__ out)
{
    __shared__ float red[8][16][REDS];   // k-split partials (padded)
    __shared__ unsigned s_done;          // monotonic completed-epoch flag

    const int tid  = threadIdx.x;
    const int bid  = blockIdx.x;
    const int grp  = bid >> 6;          // batch group 0/1
    const int lb   = bid & 63;          // local block in group
    const int j0   = lb * JPB;          // 8 h-cols
    const int w    = tid >> 5;          // K-chunk 0..7
    const int lane = tid & 31;
    const int g    = lane >> 2;         // 0..7
    const int tig  = lane & 3;          // 0..3

    // ---- one-time: Wh B-fragments in registers (hi/lo), 4 n-tiles ----
    uint2 bh[4][4], bl[4][4];
#pragma unroll
    for (int nt = 0; nt < 4; nt++) {
        int wcol = (g & 3) * 512 + j0 + 2 * nt + (g >> 2);
#pragma unroll
        for (int kt = 0; kt < 4; kt++) {
            int k0 = (4 * w + kt) * 16;
            float w00 = Wh[(size_t)(k0 + 2 * tig) * G4 + wcol];
            float w01 = Wh[(size_t)(k0 + 2 * tig + 1) * G4 + wcol];
            float w10 = Wh[(size_t)(k0 + 8 + 2 * tig) * G4 + wcol];
            float w11 = Wh[(size_t)(k0 + 8 + 2 * tig + 1) * G4 + wcol];
            __nv_bfloat16 h00, h01, h10, h11, l00, l01, l10, l11;
            split1(w00, h00, l00); split1(w01, h01, l01);
            split1(w10, h10, l10); split1(w11, h11, l11);
            bh[nt][kt].x = ((uint32_t)__bfloat16_as_ushort(h01) << 16) |
                           __bfloat16_as_ushort(h00);
            bh[nt][kt].y = ((uint32_t)__bfloat16_as_ushort(h11) << 16) |
                           __bfloat16_as_ushort(h10);
            bl[nt][kt].x = ((uint32_t)__bfloat16_as_ushort(l01) << 16) |
                           __bfloat16_as_ushort(l00);
            bl[nt][kt].y = ((uint32_t)__bfloat16_as_ushort(l11) << 16) |
                           __bfloat16_as_ushort(l10);
        }
    }

    // ---- gate-thread geometry (tid < 128): one h-value (gn, f) each ----
    const int gn  = tid >> 3;           // local batch row 0..15
    const int jl  = tid & 7;            // 0..7
    const int f   = j0 + jl;            // global h column
    const int nglob = grp * NBG + gn;   // global batch row
    const int w_r    = gn;              // m16 row
    const int w_ktg  = f >> 4;
    const int w_kc   = f & 15;
    const int w_lane = (w_r & 7) * 4 + ((w_kc & 7) >> 1);
    const int w_reg  = ((w_kc & 8) ? 2 : 0) + ((w_r & 8) ? 1 : 0);
    uint8_t* whi_p = (uint8_t*)&g_hfragHI[0][grp][w_ktg][w_lane]
                     + 4 * w_reg + 2 * (f & 1);
    uint8_t* wlo_p = (uint8_t*)&g_hfragLO[0][grp][w_ktg][w_lane]
                     + 4 * w_reg + 2 * (f & 1);
    const size_t fragbuf_bytes = sizeof(g_hfragHI[0]);  // stride buf0 -> buf1

    float c_st = 0.0f;

    // ---- init h0 fragments (buffer 0), arrive epoch 1 on own group ----
    if (tid == 0) s_done = 0u;
    if (tid < 128) {
        float v = h0[(size_t)nglob * HH + f];
        __nv_bfloat16 hb, lb2;
        split1(v, hb, lb2);
        *(unsigned short*)whi_p = __bfloat16_as_ushort(hb);
        *(unsigned short*)wlo_p = __bfloat16_as_ushort(lb2);
    }
    __syncthreads();
    if (tid == 0) cnt_arrive_g(grp);

    // ---- xw mapping (gate threads): 4 scalar loads, one per gate ----
    const size_t xw_row = (size_t)nglob * TT * G4 + j0 + jl;

    float xw[4];
    if (tid < 128) {
#pragma unroll
        for (int q = 0; q < 4; q++)
            xw[q] = __ldcg(&g_xw[xw_row + q * 512]);
    }

    for (int t = 0; t < TT; t++) {
        // prefetch next step's xw (independent of sync)
        float nxw[4];
        if (tid < 128) {
            size_t toff = (size_t)((t + 1 < TT) ? t + 1 : t) * G4;
#pragma unroll
            for (int q = 0; q < 4; q++)
                nxw[q] = __ldcg(&g_xw[xw_row + toff + q * 512]);
        }

        // wait for own group's h_t: dual global pollers; other warps spin
        // on the smem epoch flag (LDS-local) and proceed per-warp.
        if (lane == 0) {
            if (tid == 0 || tid == 128) {
                cnt_wait_dual_g(grp, &s_done, (unsigned)(t + 1));
            } else {
                unsigned d;
                do { d = *(volatile unsigned*)&s_done; }
                while ((int)(d - (unsigned)(t + 1)) < 0);
            }
        }
        __syncwarp();

        // load h_t A-fragments (m16: single tile per ktile)
        const int p = t & 1;
        uint4 ahi[4], alo[4];
#pragma unroll
        for (int kt = 0; kt < 4; kt++) {
            ahi[kt] = __ldcg(&g_hfragHI[p][grp][4 * w + kt][lane]);
            alo[kt] = __ldcg(&g_hfragLO[p][grp][4 * w + kt][lane]);
        }

        // split-term MMA, two accumulator sets
        float acc[4][4], acl[4][4];
#pragma unroll
        for (int nt = 0; nt < 4; nt++)
#pragma unroll
            for (int q = 0; q < 4; q++) { acc[nt][q] = 0.0f; acl[nt][q] = 0.0f; }

#pragma unroll
        for (int kt = 0; kt < 4; kt++)
#pragma unroll
            for (int nt = 0; nt < 4; nt++) {
                mma_bf16(acc[nt], (const uint32_t*)&ahi[kt],
                         bh[nt][kt].x, bh[nt][kt].y);
                mma_bf16(acc[nt], (const uint32_t*)&ahi[kt],
                         bl[nt][kt].x, bl[nt][kt].y);
                mma_bf16(acl[nt], (const uint32_t*)&alo[kt],
                         bh[nt][kt].x, bh[nt][kt].y);
            }

        // store k-split partials (merge lo-term); D rows g and g+8
#pragma unroll
        for (int nt = 0; nt < 4; nt++) {
            *(float2*)&red[w][g][nt * 8 + tig * 2] =
                make_float2(acc[nt][0] + acl[nt][0], acc[nt][1] + acl[nt][1]);
            *(float2*)&red[w][g + 8][nt * 8 + tig * 2] =
                make_float2(acc[nt][2] + acl[nt][2], acc[nt][3] + acl[nt][3]);
        }
        __syncthreads();

        // gate threads: float4 reduce + gates + publish h_{t+1}
        float hn;
        if (tid < 128) {
            float s0 = xw[0], s1 = xw[1], s2 = xw[2], s3 = xw[3];
#pragma unroll
            for (int kg = 0; kg < 8; kg++) {
                float4 r = *(const float4*)&red[kg][gn][jl * 4];
                s0 += r.x; s1 += r.y; s2 += r.z; s3 += r.w;
            }

            float gi = sigmoid_f(s0);
            float gf = sigmoid_f(s1);
            float go = sigmoid_f(s2);
            float gg = tanh_f(s3);

            c_st = fmaf(gf, c_st, gi * gg);
            hn = go * tanh_f(c_st);

            __nv_bfloat16 hb, lb2;
            split1(hn, hb, lb2);
            size_t boff = (size_t)((t + 1) & 1) * fragbuf_bytes;
            *(unsigned short*)(whi_p + boff) = __bfloat16_as_ushort(hb);
            *(unsigned short*)(wlo_p + boff) = __bfloat16_as_ushort(lb2);
        }
        // only publishers (warps 0-3) need ordering before the arrive
        asm volatile("bar.sync 1, 128;" ::: "memory");
        if (tid == 0) cnt_arrive_g(grp);   // epoch t+2

        // out store AFTER arrive — off the fence-drain path
        if (tid < 128) {
            out[((size_t)nglob * TT + t) * HH + f] = hn;
#pragma unroll
            for (int q = 0; q < 4; q++) xw[q] = nxw[q];
        }
    }
}

// ---------------------------------------------------------------------------
// kernel_launch
// ---------------------------------------------------------------------------
extern "C" void kernel_launch(void* const* d_in, const int* in_sizes, int n_in,
                              void* d_out, int out_size)
{
    const float* x  = (const float*)d_in[0];  // (32, 1024, 512)
    const float* h0 = (const float*)d_in[1];  // (32, 512)
    const float* Wx = (const float*)d_in[2];  // (512, 2048)
    const float* Wh = (const float*)d_in[3];  // (512, 2048)
    const float* b  = (const float*)d_in[4];  // (2048,)
    float* out = (float*)d_out;               // (32, 1024, 512)

    (void)in_sizes; (void)n_in; (void)out_size;

    // zero group counters (in-graph memset node, stream-ordered before kernels)
    void* cnt_ptr = nullptr;
    cudaGetSymbolAddress(&cnt_ptr, g_cntG);
    cudaMemsetAsync(cnt_ptr, 0, sizeof(unsigned) * 2 * 8);

    // Phase 1: split Wx, then fused-convert tensor-core GEMM (x read as fp32)
    size_t nw4 = (size_t)DD * G4 / 4;
    split_kernel_w<<<(unsigned)((nw4 + 255) / 256), 256>>>(Wx);

    dim3 g1(G4 / 128, MROWS / 64);  // (16, 512)
    gemm_xw_mma<<<g1, 256>>>(x, b);

    // Phase 2: persistent tensor-core recurrence, 2 independent batch groups
    lstm_rec_mma<<<RBLOCKS, RTHREADS>>>(h0, Wh, out);
}